// round 2
// baseline (speedup 1.0000x reference)
#include <cuda_runtime.h>
#include <math.h>

#define B_ 32
#define T_ 64
#define S_ 64
#define V_ 32000
#define E_ 512
#define U_ 1024

// ---------------- scratch (static device globals; no allocs) ----------------
__device__ float g_emb [B_*T_*E_];   // 4 MB  embedded decoder inputs
__device__ float g_keys[B_*S_*U_];   // 8 MB  Bahdanau keys = enc @ Wk
__device__ float g_attn[B_*T_*U_];   // 8 MB  attention outputs per step (A of final GEMM)
__device__ float g_z   [B_*4*U_];    // 512 KB LSTM pre-activations
__device__ float g_h   [B_*U_];
__device__ float g_c   [B_*U_];
__device__ float g_q   [B_*U_];
__device__ float g_ctx [B_*U_];

__device__ __forceinline__ float tanh_fast(float x){
    float r; asm("tanh.approx.f32 %0, %1;" : "=f"(r) : "f"(x)); return r;
}
__device__ __forceinline__ float sigmoid_acc(float x){
    return 1.0f / (1.0f + expf(-x));
}

// ---------------- init h/c ----------------
__global__ void init_hc(const float* __restrict__ h0, const float* __restrict__ c0){
    int i = blockIdx.x * blockDim.x + threadIdx.x;
    if (i < B_*U_){ g_h[i] = h0[i]; g_c[i] = c0[i]; }
}

// ---------------- embedding gather (dec_in = [<start>=1, y[:, :-1]]) -------
__global__ void embed_gather(const int* __restrict__ y, const float* __restrict__ emb){
    int bt = blockIdx.x;            // 0..2047
    int b = bt / T_, t = bt % T_;
    int tok = (t == 0) ? 1 : y[b*T_ + t - 1];
    const float4* src = (const float4*)(emb + (long long)tok * E_);
    float4* dst = (float4*)(g_emb + (long long)bt * E_);
    int i = threadIdx.x;            // 128 threads, E_/4 = 128
    if (i < E_/4) dst[i] = src[i];
}

// ---------------- generic fp32 SGEMM: C[M,N] = A[M,K] @ B[K,N] (+bias) -----
// BM=BN=64, BK=16, 256 threads, 4x4 per thread.
__global__ __launch_bounds__(256)
void sgemm_bias(const float* __restrict__ A, const float* __restrict__ B,
                const float* __restrict__ bias, float* __restrict__ C,
                int M, int N, int K){
    __shared__ float As[16][64];
    __shared__ float Bs[16][64];
    int tid = threadIdx.x;
    int tx = tid & 15, ty = tid >> 4;
    int row0 = blockIdx.y * 64, col0 = blockIdx.x * 64;

    float acc[4][4];
    #pragma unroll
    for (int i = 0; i < 4; i++)
        #pragma unroll
        for (int j = 0; j < 4; j++) acc[i][j] = 0.0f;

    int la_r = tid >> 2;            // 0..63
    int la_c = (tid & 3) * 4;       // 0,4,8,12
    int lb_r = tid >> 4;            // 0..15
    int lb_c = (tid & 15) * 4;      // 0..60

    for (int k0 = 0; k0 < K; k0 += 16){
        float4 a4 = *(const float4*)(A + (long long)(row0 + la_r)*K + k0 + la_c);
        As[la_c+0][la_r] = a4.x; As[la_c+1][la_r] = a4.y;
        As[la_c+2][la_r] = a4.z; As[la_c+3][la_r] = a4.w;
        float4 b4 = *(const float4*)(B + (long long)(k0 + lb_r)*N + col0 + lb_c);
        *(float4*)&Bs[lb_r][lb_c] = b4;
        __syncthreads();
        #pragma unroll
        for (int k = 0; k < 16; k++){
            float ar[4], br[4];
            *(float4*)ar = *(const float4*)&As[k][ty*4];
            *(float4*)br = *(const float4*)&Bs[k][tx*4];
            #pragma unroll
            for (int i = 0; i < 4; i++)
                #pragma unroll
                for (int j = 0; j < 4; j++)
                    acc[i][j] = fmaf(ar[i], br[j], acc[i][j]);
        }
        __syncthreads();
    }

    float bv[4] = {0.f,0.f,0.f,0.f};
    if (bias){
        #pragma unroll
        for (int j = 0; j < 4; j++) bv[j] = bias[col0 + tx*4 + j];
    }
    #pragma unroll
    for (int i = 0; i < 4; i++){
        float4 o;
        o.x = acc[i][0] + bv[0]; o.y = acc[i][1] + bv[1];
        o.z = acc[i][2] + bv[2]; o.w = acc[i][3] + bv[3];
        *(float4*)(C + (long long)(row0 + ty*4 + i)*N + col0 + tx*4) = o;
    }
}

// ---------------- per-step: z = [emb_t; a_prev] @ Wx + h @ Wh + b ----------
// grid (32 jblocks, 4 bgroups), 128 threads; 8 batch accumulators per thread.
__global__ __launch_bounds__(128)
void z_step(const float* __restrict__ Wx, const float* __restrict__ Wh,
            const float* __restrict__ bias, int t){
    __shared__ float xs[8][64];
    int j  = blockIdx.x * 128 + threadIdx.x;     // 0..4095
    int b0 = blockIdx.y * 8;
    float acc[8];
    #pragma unroll
    for (int i = 0; i < 8; i++) acc[i] = 0.0f;

    const float* segp[3]; int segst[3]; const float* segW[3]; int segr0[3]; int segK[3];
    int nseg = 0;
    segp[nseg] = g_emb + t*E_;          segst[nseg] = T_*E_; segW[nseg] = Wx; segr0[nseg] = 0;  segK[nseg] = E_; nseg++;
    if (t > 0){
      segp[nseg] = g_attn + (t-1)*U_;   segst[nseg] = T_*U_; segW[nseg] = Wx; segr0[nseg] = E_; segK[nseg] = U_; nseg++;
    }
    segp[nseg] = g_h;                   segst[nseg] = U_;    segW[nseg] = Wh; segr0[nseg] = 0;  segK[nseg] = U_; nseg++;

    for (int s = 0; s < nseg; s++){
        const float* p = segp[s]; int st = segst[s];
        const float* W = segW[s]; int r0 = segr0[s]; int Ks = segK[s];
        for (int k0 = 0; k0 < Ks; k0 += 64){
            __syncthreads();
            #pragma unroll
            for (int i = 0; i < 4; i++){
                int e = threadIdx.x + i*128;
                int bb = e >> 6, k = e & 63;
                xs[bb][k] = p[(long long)(b0+bb)*st + k0 + k];
            }
            __syncthreads();
            #pragma unroll 4
            for (int k = 0; k < 64; k += 4){
                const float* wp = W + (long long)(r0 + k0 + k)*4096 + j;
                float w0 = wp[0], w1 = wp[4096], w2 = wp[2*4096], w3 = wp[3*4096];
                #pragma unroll
                for (int bb = 0; bb < 8; bb++){
                    float4 xv = *(const float4*)&xs[bb][k];
                    acc[bb] = fmaf(xv.x, w0, acc[bb]);
                    acc[bb] = fmaf(xv.y, w1, acc[bb]);
                    acc[bb] = fmaf(xv.z, w2, acc[bb]);
                    acc[bb] = fmaf(xv.w, w3, acc[bb]);
                }
            }
        }
    }
    float bj = bias[j];
    #pragma unroll
    for (int bb = 0; bb < 8; bb++)
        g_z[(long long)(b0+bb)*4096 + j] = acc[bb] + bj;
}

// ---------------- per-step: LSTM pointwise (TF gate order i,j,f,o) ---------
__global__ void lstm_pt(){
    int idx = blockIdx.x * blockDim.x + threadIdx.x;   // 32768
    if (idx >= B_*U_) return;
    int b = idx >> 10, u = idx & 1023;
    const float* z = g_z + (long long)b*4096;
    float zi = z[u], zj = z[U_+u], zf = z[2*U_+u], zo = z[3*U_+u];
    float c  = g_c[idx];
    float cn = sigmoid_acc(zf + 1.0f) * c + sigmoid_acc(zi) * tanhf(zj);
    g_c[idx] = cn;
    g_h[idx] = sigmoid_acc(zo) * tanhf(cn);
}

// ---------------- per-step: q = h @ Wq -------------------------------------
// grid (8 jblocks, 8 bgroups), 128 threads; 4 batch accumulators.
__global__ __launch_bounds__(128)
void q_step(const float* __restrict__ Wq){
    __shared__ float xs[4][64];
    int j  = blockIdx.x * 128 + threadIdx.x;
    int b0 = blockIdx.y * 4;
    float acc[4] = {0.f,0.f,0.f,0.f};
    for (int k0 = 0; k0 < U_; k0 += 64){
        __syncthreads();
        #pragma unroll
        for (int i = 0; i < 2; i++){
            int e = threadIdx.x + i*128;
            int bb = e >> 6, k = e & 63;
            xs[bb][k] = g_h[(long long)(b0+bb)*U_ + k0 + k];
        }
        __syncthreads();
        #pragma unroll 4
        for (int k = 0; k < 64; k += 4){
            const float* wp = Wq + (long long)(k0 + k)*U_ + j;
            float w0 = wp[0], w1 = wp[U_], w2 = wp[2*U_], w3 = wp[3*U_];
            #pragma unroll
            for (int bb = 0; bb < 4; bb++){
                float4 xv = *(const float4*)&xs[bb][k];
                acc[bb] = fmaf(xv.x, w0, acc[bb]);
                acc[bb] = fmaf(xv.y, w1, acc[bb]);
                acc[bb] = fmaf(xv.z, w2, acc[bb]);
                acc[bb] = fmaf(xv.w, w3, acc[bb]);
            }
        }
    }
    #pragma unroll
    for (int bb = 0; bb < 4; bb++)
        g_q[(long long)(b0+bb)*U_ + j] = acc[bb];
}

// ---------------- per-step: scores + softmax + context ---------------------
// grid (32 batches), 256 threads.
__global__ __launch_bounds__(256)
void attn_step(const float* __restrict__ enc, const float* __restrict__ v){
    int b = blockIdx.x;
    __shared__ float q_s[U_];
    __shared__ float sc_s[S_];
    __shared__ float al_s[S_];
    int tid = threadIdx.x;
    for (int u = tid; u < U_; u += 256) q_s[u] = g_q[(long long)b*U_ + u];
    __syncthreads();

    int warp = tid >> 5, lane = tid & 31;
    #pragma unroll
    for (int si = 0; si < 8; si++){
        int s = warp*8 + si;
        const float* kp = g_keys + (long long)(b*S_ + s)*U_;
        float p = 0.f;
        for (int u = lane; u < U_; u += 32)
            p = fmaf(tanh_fast(kp[u] + q_s[u]), v[u], p);
        #pragma unroll
        for (int off = 16; off; off >>= 1)
            p += __shfl_xor_sync(0xffffffffu, p, off);
        if (lane == 0) sc_s[s] = p;
    }
    __syncthreads();

    if (warp == 0){
        float s0 = sc_s[lane], s1 = sc_s[lane+32];
        float m = fmaxf(s0, s1);
        #pragma unroll
        for (int off = 16; off; off >>= 1)
            m = fmaxf(m, __shfl_xor_sync(0xffffffffu, m, off));
        float e0 = expf(s0 - m), e1 = expf(s1 - m);
        float sum = e0 + e1;
        #pragma unroll
        for (int off = 16; off; off >>= 1)
            sum += __shfl_xor_sync(0xffffffffu, sum, off);
        float inv = 1.0f / sum;
        al_s[lane]    = e0 * inv;
        al_s[lane+32] = e1 * inv;
    }
    __syncthreads();

    for (int e = tid; e < U_; e += 256){
        const float* ep = enc + (long long)b*S_*U_ + e;
        float a = 0.f;
        #pragma unroll
        for (int s = 0; s < S_; s++)
            a = fmaf(al_s[s], ep[(long long)s*U_], a);
        g_ctx[(long long)b*U_ + e] = a;
    }
}

// ---------------- per-step: a_new = [h; ctx] @ Wa --------------------------
// grid (8 jblocks, 8 bgroups), 128 threads; 4 batch accumulators.
__global__ __launch_bounds__(128)
void attnout_step(const float* __restrict__ Wa, int t){
    __shared__ float xs[4][64];
    int j  = blockIdx.x * 128 + threadIdx.x;
    int b0 = blockIdx.y * 4;
    float acc[4] = {0.f,0.f,0.f,0.f};
    for (int half = 0; half < 2; half++){
        const float* src = half ? g_ctx : g_h;
        int r0 = half * U_;
        for (int k0 = 0; k0 < U_; k0 += 64){
            __syncthreads();
            #pragma unroll
            for (int i = 0; i < 2; i++){
                int e = threadIdx.x + i*128;
                int bb = e >> 6, k = e & 63;
                xs[bb][k] = src[(long long)(b0+bb)*U_ + k0 + k];
            }
            __syncthreads();
            #pragma unroll 4
            for (int k = 0; k < 64; k += 4){
                const float* wp = Wa + (long long)(r0 + k0 + k)*U_ + j;
                float w0 = wp[0], w1 = wp[U_], w2 = wp[2*U_], w3 = wp[3*U_];
                #pragma unroll
                for (int bb = 0; bb < 4; bb++){
                    float4 xv = *(const float4*)&xs[bb][k];
                    acc[bb] = fmaf(xv.x, w0, acc[bb]);
                    acc[bb] = fmaf(xv.y, w1, acc[bb]);
                    acc[bb] = fmaf(xv.z, w2, acc[bb]);
                    acc[bb] = fmaf(xv.w, w3, acc[bb]);
                }
            }
        }
    }
    #pragma unroll
    for (int bb = 0; bb < 4; bb++)
        g_attn[(long long)(b0+bb)*T_*U_ + (long long)t*U_ + j] = acc[bb];
}

// ---------------- launch -----------------------------------------------------
extern "C" void kernel_launch(void* const* d_in, const int* in_sizes, int n_in,
                              void* d_out, int out_size){
    const int*   y     = (const int*)  d_in[0];
    const float* h0    = (const float*)d_in[1];
    const float* c0    = (const float*)d_in[2];
    const float* enc   = (const float*)d_in[3];
    const float* emb   = (const float*)d_in[4];
    const float* Wx    = (const float*)d_in[5];
    const float* Wh    = (const float*)d_in[6];
    const float* bvec  = (const float*)d_in[7];
    const float* Wk    = (const float*)d_in[8];
    const float* Wq    = (const float*)d_in[9];
    const float* v_att = (const float*)d_in[10];
    const float* Wa    = (const float*)d_in[11];
    const float* Wout  = (const float*)d_in[12];
    const float* bout  = (const float*)d_in[13];
    float* out = (float*)d_out;

    void* p;
    cudaGetSymbolAddress(&p, g_keys); float* keys_p = (float*)p;
    cudaGetSymbolAddress(&p, g_attn); float* attn_p = (float*)p;

    init_hc<<<128, 256>>>(h0, c0);
    embed_gather<<<B_*T_, 128>>>(y, emb);

    // keys = enc @ Wk : [2048,1024] x [1024,1024]
    sgemm_bias<<<dim3(U_/64, (B_*S_)/64), 256>>>(enc, Wk, nullptr, keys_p,
                                                 B_*S_, U_, U_);

    for (int t = 0; t < T_; t++){
        z_step<<<dim3(32, 4), 128>>>(Wx, Wh, bvec, t);
        lstm_pt<<<128, 256>>>();
        q_step<<<dim3(8, 8), 128>>>(Wq);
        attn_step<<<32, 256>>>(enc, v_att);
        attnout_step<<<dim3(8, 8), 128>>>(Wa, t);
    }

    // logits = attn_seq @ Wout + bout : [2048,1024] x [1024,32000]
    sgemm_bias<<<dim3(V_/64, (B_*T_)/64), 256>>>(attn_p, Wout, bout, out,
                                                 B_*T_, V_, U_);
}

// round 6
// speedup vs baseline: 4.3928x; 4.3928x over previous
#include <cuda_runtime.h>
#include <math.h>

#define B_ 32
#define T_ 64
#define S_ 64
#define V_ 32000
#define E_ 512
#define U_ 1024

// ---------------- scratch (static device globals; no allocs) ----------------
__device__ float g_emb  [B_*T_*E_];      // embedded decoder inputs
__device__ float g_keys [B_*S_*U_];      // Bahdanau keys = enc @ Wk
__device__ float g_attn [B_*T_*U_];      // attention outputs (A of final GEMM)
__device__ float g_zpart[20*B_*4*U_];    // z split-k partials
__device__ float g_qpart[16*B_*U_];      // q split-k partials
__device__ float g_apart[16*B_*U_];      // attnout split-k partials
__device__ float g_aprev[B_*U_];         // reduced a_{t-1}
__device__ float g_h    [B_*U_];
__device__ float g_c    [B_*U_];
__device__ float g_ctx  [B_*U_];

__device__ __forceinline__ float tanh_fast(float x){
    float r; asm("tanh.approx.f32 %0, %1;" : "=f"(r) : "f"(x)); return r;
}
__device__ __forceinline__ float sigmoid_acc(float x){
    return 1.0f / (1.0f + expf(-x));
}

// ---------------- init h/c ----------------
__global__ void init_hc(const float* __restrict__ h0, const float* __restrict__ c0){
    int i = blockIdx.x * blockDim.x + threadIdx.x;
    if (i < B_*U_){ g_h[i] = h0[i]; g_c[i] = c0[i]; }
}

// ---------------- embedding gather (dec_in = [<start>=1, y[:, :-1]]) -------
__global__ void embed_gather(const int* __restrict__ y, const float* __restrict__ emb){
    int bt = blockIdx.x;            // 0..2047
    int b = bt / T_, t = bt % T_;
    int tok = (t == 0) ? 1 : y[b*T_ + t - 1];
    const float4* src = (const float4*)(emb + (long long)tok * E_);
    float4* dst = (float4*)(g_emb + (long long)bt * E_);
    int i = threadIdx.x;            // 128 threads, E_/4 = 128
    if (i < E_/4) dst[i] = src[i];
}

// ---------------- prep: reduce attnout partials of step t-1 ----------------
// grid 32 (batch), 256 threads. t=0: zero a_prev. t=64: only writes g_attn[63].
__global__ void prep_step(int t){
    int b = blockIdx.x;
    for (int u = threadIdx.x; u < U_; u += 256){
        if (t == 0){
            g_aprev[b*U_ + u] = 0.0f;
        } else {
            float s = 0.0f;
            #pragma unroll
            for (int p = 0; p < 16; p++)
                s += g_apart[(p*B_ + b)*U_ + u];
            g_attn[((long long)b*T_ + (t-1))*U_ + u] = s;
            g_aprev[b*U_ + u] = s;
        }
    }
}

// ---------------- z split-k partial: 128 j x 128 k x 32 b per block --------
// grid (32 jblocks, 20 kblocks), 128 threads, 32 accumulators/thread.
__global__ __launch_bounds__(128)
void z_partial(const float* __restrict__ Wx, const float* __restrict__ Wh, int t){
    __shared__ float xs[128][36];
    int tid = threadIdx.x;
    int kb  = blockIdx.y;
    int j   = blockIdx.x * 128 + tid;

    const float* xp; long long xst; const float* wp;
    if (kb < 4){        // emb segment (512 = 4*128)
        xp  = g_emb + (long long)t*E_ + kb*128;
        xst = (long long)T_*E_;
        wp  = Wx + (long long)(kb*128)*4096;
    } else if (kb < 12){ // a_prev segment (1024 = 8*128)
        xp  = g_aprev + (kb-4)*128;
        xst = U_;
        wp  = Wx + (long long)(512 + (kb-4)*128)*4096;
    } else {             // h segment via Wh (1024 = 8*128)
        xp  = g_h + (kb-12)*128;
        xst = U_;
        wp  = Wh + (long long)((kb-12)*128)*4096;
    }

    // stage x[32 b][128 k] -> xs[k][b]
    int b = tid >> 2, kq = tid & 3;
    #pragma unroll
    for (int i = 0; i < 8; i++){
        int k = kq*32 + i*4;
        float4 v = *(const float4*)(xp + b*xst + k);
        xs[k+0][b] = v.x; xs[k+1][b] = v.y; xs[k+2][b] = v.z; xs[k+3][b] = v.w;
    }
    __syncthreads();

    float acc[32];
    #pragma unroll
    for (int i = 0; i < 32; i++) acc[i] = 0.0f;

    const float* w = wp + j;
    #pragma unroll 4
    for (int k = 0; k < 128; k += 4){
        float w0 = w[(long long)(k+0)*4096];
        float w1 = w[(long long)(k+1)*4096];
        float w2 = w[(long long)(k+2)*4096];
        float w3 = w[(long long)(k+3)*4096];
        #pragma unroll
        for (int kk = 0; kk < 4; kk++){
            float wk = (kk==0)?w0:(kk==1)?w1:(kk==2)?w2:w3;
            #pragma unroll
            for (int b4 = 0; b4 < 8; b4++){
                float4 xv = *(const float4*)&xs[k+kk][b4*4];
                acc[b4*4+0] = fmaf(xv.x, wk, acc[b4*4+0]);
                acc[b4*4+1] = fmaf(xv.y, wk, acc[b4*4+1]);
                acc[b4*4+2] = fmaf(xv.z, wk, acc[b4*4+2]);
                acc[b4*4+3] = fmaf(xv.w, wk, acc[b4*4+3]);
            }
        }
    }
    #pragma unroll
    for (int bb = 0; bb < 32; bb++)
        g_zpart[((long long)kb*B_ + bb)*4096 + j] = acc[bb];
}

// ---------------- LSTM pointwise + z reduction (TF gate order i,j,f,o) -----
__global__ void lstm_pt(const float* __restrict__ bias){
    int idx = blockIdx.x * blockDim.x + threadIdx.x;   // 32768
    if (idx >= B_*U_) return;
    int b = idx >> 10, u = idx & 1023;
    float zi = bias[u], zj = bias[U_+u], zf = bias[2*U_+u], zo = bias[3*U_+u];
    #pragma unroll
    for (int p = 0; p < 20; p++){
        const float* zp = g_zpart + ((long long)p*B_ + b)*4096;
        zi += zp[u]; zj += zp[U_+u]; zf += zp[2*U_+u]; zo += zp[3*U_+u];
    }
    float c  = g_c[idx];
    float cn = sigmoid_acc(zf + 1.0f) * c + sigmoid_acc(zi) * tanhf(zj);
    g_c[idx] = cn;
    g_h[idx] = sigmoid_acc(zo) * tanhf(cn);
}

// ---------------- q split-k partial: 128 j x 64 k x 32 b -------------------
// grid (8 jblocks, 16 kblocks), 128 threads.
__global__ __launch_bounds__(128)
void q_partial(const float* __restrict__ Wq){
    __shared__ float xs[64][36];
    int tid = threadIdx.x;
    int kb  = blockIdx.y;
    int j   = blockIdx.x * 128 + tid;
    int r0  = kb * 64;

    int b = tid >> 2, kq = tid & 3;
    #pragma unroll
    for (int i = 0; i < 4; i++){
        int k = kq*16 + i*4;
        float4 v = *(const float4*)(g_h + b*U_ + r0 + k);
        xs[k+0][b] = v.x; xs[k+1][b] = v.y; xs[k+2][b] = v.z; xs[k+3][b] = v.w;
    }
    __syncthreads();

    float acc[32];
    #pragma unroll
    for (int i = 0; i < 32; i++) acc[i] = 0.0f;

    const float* w = Wq + (long long)r0*U_ + j;
    #pragma unroll 4
    for (int k = 0; k < 64; k += 4){
        float w0 = w[(long long)(k+0)*U_];
        float w1 = w[(long long)(k+1)*U_];
        float w2 = w[(long long)(k+2)*U_];
        float w3 = w[(long long)(k+3)*U_];
        #pragma unroll
        for (int kk = 0; kk < 4; kk++){
            float wk = (kk==0)?w0:(kk==1)?w1:(kk==2)?w2:w3;
            #pragma unroll
            for (int b4 = 0; b4 < 8; b4++){
                float4 xv = *(const float4*)&xs[k+kk][b4*4];
                acc[b4*4+0] = fmaf(xv.x, wk, acc[b4*4+0]);
                acc[b4*4+1] = fmaf(xv.y, wk, acc[b4*4+1]);
                acc[b4*4+2] = fmaf(xv.z, wk, acc[b4*4+2]);
                acc[b4*4+3] = fmaf(xv.w, wk, acc[b4*4+3]);
            }
        }
    }
    #pragma unroll
    for (int bb = 0; bb < 32; bb++)
        g_qpart[((long long)kb*B_ + bb)*U_ + j] = acc[bb];
}

// ---------------- scores + softmax + context (q-reduce fused) --------------
// grid 32 (batch), 512 threads.
__global__ __launch_bounds__(512)
void attn_step(const float* __restrict__ enc, const float* __restrict__ v){
    int b = blockIdx.x;
    __shared__ float q_s[U_];
    __shared__ float sc_s[S_];
    __shared__ float al_s[S_];
    int tid = threadIdx.x;

    // q = sum of 16 partials
    for (int u = tid; u < U_; u += 512){
        float s = 0.0f;
        #pragma unroll
        for (int p = 0; p < 16; p++)
            s += g_qpart[((long long)p*B_ + b)*U_ + u];
        q_s[u] = s;
    }
    __syncthreads();

    int warp = tid >> 5, lane = tid & 31;
    #pragma unroll
    for (int si = 0; si < 4; si++){
        int s = warp*4 + si;
        const float* kp = g_keys + (long long)(b*S_ + s)*U_;
        float p = 0.f;
        for (int u = lane; u < U_; u += 32)
            p = fmaf(tanh_fast(kp[u] + q_s[u]), v[u], p);
        #pragma unroll
        for (int off = 16; off; off >>= 1)
            p += __shfl_xor_sync(0xffffffffu, p, off);
        if (lane == 0) sc_s[s] = p;
    }
    __syncthreads();

    if (warp == 0){
        float s0 = sc_s[lane], s1 = sc_s[lane+32];
        float m = fmaxf(s0, s1);
        #pragma unroll
        for (int off = 16; off; off >>= 1)
            m = fmaxf(m, __shfl_xor_sync(0xffffffffu, m, off));
        float e0 = expf(s0 - m), e1 = expf(s1 - m);
        float sum = e0 + e1;
        #pragma unroll
        for (int off = 16; off; off >>= 1)
            sum += __shfl_xor_sync(0xffffffffu, sum, off);
        float inv = 1.0f / sum;
        al_s[lane]    = e0 * inv;
        al_s[lane+32] = e1 * inv;
    }
    __syncthreads();

    for (int e = tid; e < U_; e += 512){
        const float* ep = enc + (long long)b*S_*U_ + e;
        float a = 0.f;
        #pragma unroll 16
        for (int s = 0; s < S_; s++)
            a = fmaf(al_s[s], ep[(long long)s*U_], a);
        g_ctx[(long long)b*U_ + e] = a;
    }
}

// ---------------- attnout split-k partial: a_new = [h; ctx] @ Wa -----------
// grid (8 jblocks, 16 kblocks of 128), 128 threads.
__global__ __launch_bounds__(128)
void attnout_partial(const float* __restrict__ Wa){
    __shared__ float xs[128][36];
    int tid = threadIdx.x;
    int kb  = blockIdx.y;
    int j   = blockIdx.x * 128 + tid;

    const float* xp = (kb < 8) ? (g_h + kb*128) : (g_ctx + (kb-8)*128);
    const float* wp = Wa + (long long)(kb*128)*U_;

    int b = tid >> 2, kq = tid & 3;
    #pragma unroll
    for (int i = 0; i < 8; i++){
        int k = kq*32 + i*4;
        float4 v = *(const float4*)(xp + b*U_ + k);
        xs[k+0][b] = v.x; xs[k+1][b] = v.y; xs[k+2][b] = v.z; xs[k+3][b] = v.w;
    }
    __syncthreads();

    float acc[32];
    #pragma unroll
    for (int i = 0; i < 32; i++) acc[i] = 0.0f;

    const float* w = wp + j;
    #pragma unroll 4
    for (int k = 0; k < 128; k += 4){
        float w0 = w[(long long)(k+0)*U_];
        float w1 = w[(long long)(k+1)*U_];
        float w2 = w[(long long)(k+2)*U_];
        float w3 = w[(long long)(k+3)*U_];
        #pragma unroll
        for (int kk = 0; kk < 4; kk++){
            float wk = (kk==0)?w0:(kk==1)?w1:(kk==2)?w2:w3;
            #pragma unroll
            for (int b4 = 0; b4 < 8; b4++){
                float4 xv = *(const float4*)&xs[k+kk][b4*4];
                acc[b4*4+0] = fmaf(xv.x, wk, acc[b4*4+0]);
                acc[b4*4+1] = fmaf(xv.y, wk, acc[b4*4+1]);
                acc[b4*4+2] = fmaf(xv.z, wk, acc[b4*4+2]);
                acc[b4*4+3] = fmaf(xv.w, wk, acc[b4*4+3]);
            }
        }
    }
    #pragma unroll
    for (int bb = 0; bb < 32; bb++)
        g_apart[((long long)kb*B_ + bb)*U_ + j] = acc[bb];
}

// ---------------- 128x128x16 SGEMM, 8x8/thread, reg-staged prefetch --------
// grid (M/128 in x, N/128 in y). C = A@B (+bias).
__global__ __launch_bounds__(256)
void sgemm128(const float* __restrict__ A, const float* __restrict__ Bm,
              const float* __restrict__ bias, float* __restrict__ C,
              int M, int N, int K){
    __shared__ float As[16][132];
    __shared__ float Bs[16][132];
    int tid = threadIdx.x;
    int tx = tid & 15, ty = tid >> 4;
    int row0 = blockIdx.x * 128, col0 = blockIdx.y * 128;

    int m0 = tid >> 2, kq = tid & 3;      // A staging
    int kr = tid >> 5, n4 = tid & 31;     // B staging

    float acc[8][8];
    #pragma unroll
    for (int i = 0; i < 8; i++)
        #pragma unroll
        for (int j = 0; j < 8; j++) acc[i][j] = 0.0f;

    const float* Ap  = A  + (long long)(row0 + m0)*K + kq*4;
    const float* Ap2 = Ap + (long long)64*K;
    const float* Bp  = Bm + (long long)kr*N + col0 + n4*4;
    const float* Bp2 = Bp + (long long)8*N;

    float4 pa0 = *(const float4*)Ap;
    float4 pa1 = *(const float4*)Ap2;
    float4 pb0 = *(const float4*)Bp;
    float4 pb1 = *(const float4*)Bp2;

    int nk = K >> 4;
    for (int kt = 0; kt < nk; kt++){
        As[kq*4+0][m0]    = pa0.x; As[kq*4+1][m0]    = pa0.y;
        As[kq*4+2][m0]    = pa0.z; As[kq*4+3][m0]    = pa0.w;
        As[kq*4+0][m0+64] = pa1.x; As[kq*4+1][m0+64] = pa1.y;
        As[kq*4+2][m0+64] = pa1.z; As[kq*4+3][m0+64] = pa1.w;
        *(float4*)&Bs[kr][n4*4]   = pb0;
        *(float4*)&Bs[kr+8][n4*4] = pb1;
        __syncthreads();

        if (kt + 1 < nk){
            pa0 = *(const float4*)(Ap  + (kt+1)*16);
            pa1 = *(const float4*)(Ap2 + (kt+1)*16);
            pb0 = *(const float4*)(Bp  + (long long)(kt+1)*16*N);
            pb1 = *(const float4*)(Bp2 + (long long)(kt+1)*16*N);
        }

        #pragma unroll
        for (int k = 0; k < 16; k++){
            float a[8], bb[8];
            *(float4*)&a[0]  = *(const float4*)&As[k][ty*8];
            *(float4*)&a[4]  = *(const float4*)&As[k][ty*8+4];
            *(float4*)&bb[0] = *(const float4*)&Bs[k][tx*8];
            *(float4*)&bb[4] = *(const float4*)&Bs[k][tx*8+4];
            #pragma unroll
            for (int i = 0; i < 8; i++)
                #pragma unroll
                for (int j = 0; j < 8; j++)
                    acc[i][j] = fmaf(a[i], bb[j], acc[i][j]);
        }
        __syncthreads();
    }

    float bv[8];
    #pragma unroll
    for (int j = 0; j < 8; j++) bv[j] = bias ? bias[col0 + tx*8 + j] : 0.0f;

    #pragma unroll
    for (int i = 0; i < 8; i++){
        float* cp = C + (long long)(row0 + ty*8 + i)*N + col0 + tx*8;
        float4 o0, o1;
        o0.x = acc[i][0]+bv[0]; o0.y = acc[i][1]+bv[1];
        o0.z = acc[i][2]+bv[2]; o0.w = acc[i][3]+bv[3];
        o1.x = acc[i][4]+bv[4]; o1.y = acc[i][5]+bv[5];
        o1.z = acc[i][6]+bv[6]; o1.w = acc[i][7]+bv[7];
        *(float4*)cp       = o0;
        *(float4*)(cp + 4) = o1;
    }
}

// ---------------- launch -----------------------------------------------------
extern "C" void kernel_launch(void* const* d_in, const int* in_sizes, int n_in,
                              void* d_out, int out_size){
    const int*   y     = (const int*)  d_in[0];
    const float* h0    = (const float*)d_in[1];
    const float* c0    = (const float*)d_in[2];
    const float* enc   = (const float*)d_in[3];
    const float* emb   = (const float*)d_in[4];
    const float* Wx    = (const float*)d_in[5];
    const float* Wh    = (const float*)d_in[6];
    const float* bvec  = (const float*)d_in[7];
    const float* Wk    = (const float*)d_in[8];
    const float* Wq    = (const float*)d_in[9];
    const float* v_att = (const float*)d_in[10];
    const float* Wa    = (const float*)d_in[11];
    const float* Wout  = (const float*)d_in[12];
    const float* bout  = (const float*)d_in[13];
    float* out = (float*)d_out;

    void* p;
    cudaGetSymbolAddress(&p, g_keys); float* keys_p = (float*)p;
    cudaGetSymbolAddress(&p, g_attn); float* attn_p = (float*)p;

    init_hc<<<128, 256>>>(h0, c0);
    embed_gather<<<B_*T_, 128>>>(y, emb);

    // keys = enc @ Wk : [2048,1024] x [1024,1024]
    sgemm128<<<dim3((B_*S_)/128, U_/128), 256>>>(enc, Wk, nullptr, keys_p,
                                                 B_*S_, U_, U_);

    for (int t = 0; t < T_; t++){
        prep_step<<<32, 256>>>(t);
        z_partial<<<dim3(32, 20), 128>>>(Wx, Wh, t);
        lstm_pt<<<128, 256>>>(bvec);
        q_partial<<<dim3(8, 16), 128>>>(Wq);
        attn_step<<<32, 512>>>(enc, v_att);
        attnout_partial<<<dim3(8, 16), 128>>>(Wa);
    }
    prep_step<<<32, 256>>>(T_);   // reduce final attnout into g_attn[:,63,:]

    // logits = attn_seq @ Wout + bout : [2048,1024] x [1024,32000]
    sgemm128<<<dim3((B_*T_)/128, V_/128), 256>>>(attn_p, Wout, bout, out,
                                                 B_*T_, V_, U_);
}

// round 11
// speedup vs baseline: 5.2562x; 1.1966x over previous
#include <cuda_runtime.h>
#include <cuda_bf16.h>
#include <math.h>
#include <stdint.h>

#define B_ 32
#define T_ 64
#define S_ 64
#define V_ 32000
#define E_ 512
#define U_ 1024

// ---------------- scratch (static device globals; no allocs) ----------------
__device__ float g_emb  [B_*T_*E_];
__device__ float g_keys [B_*S_*U_];
__device__ float g_attn [B_*T_*U_];
__device__ float g_zpart[20*B_*4*U_];
__device__ float g_qpart[16*B_*U_];
__device__ float g_apart[16*B_*U_];
__device__ float g_aprev[B_*U_];
__device__ float g_h    [B_*U_];
__device__ float g_c    [B_*U_];
__device__ float g_ctx  [B_*U_];
// bf16-split operands for tensor-core output GEMM
__device__ __nv_bfloat16 g_Ah[B_*T_*U_];     // attn hi   [2048][1024] k-major
__device__ __nv_bfloat16 g_Al[B_*T_*U_];     // attn lo
__device__ __nv_bfloat16 g_Bh[V_*U_];        // Wout^T hi [32000][1024] n-major
__device__ __nv_bfloat16 g_Bl[V_*U_];        // Wout^T lo

__device__ __forceinline__ float tanh_fast(float x){
    float r; asm("tanh.approx.f32 %0, %1;" : "=f"(r) : "f"(x)); return r;
}
__device__ __forceinline__ float sigmoid_acc(float x){
    return 1.0f / (1.0f + expf(-x));
}

// ---------------- init h/c ----------------
__global__ void init_hc(const float* __restrict__ h0, const float* __restrict__ c0){
    int i = blockIdx.x * blockDim.x + threadIdx.x;
    if (i < B_*U_){ g_h[i] = h0[i]; g_c[i] = c0[i]; }
}

// ---------------- embedding gather ----------------
__global__ void embed_gather(const int* __restrict__ y, const float* __restrict__ emb){
    int bt = blockIdx.x;
    int b = bt / T_, t = bt % T_;
    int tok = (t == 0) ? 1 : y[b*T_ + t - 1];
    const float4* src = (const float4*)(emb + (long long)tok * E_);
    float4* dst = (float4*)(g_emb + (long long)bt * E_);
    int i = threadIdx.x;
    if (i < E_/4) dst[i] = src[i];
}

// ---------------- prep: reduce attnout partials of step t-1 ----------------
__global__ void prep_step(int t){
    int b = blockIdx.x;
    for (int u = threadIdx.x; u < U_; u += 256){
        if (t == 0){
            g_aprev[b*U_ + u] = 0.0f;
        } else {
            float s = 0.0f;
            #pragma unroll
            for (int p = 0; p < 16; p++)
                s += g_apart[(p*B_ + b)*U_ + u];
            g_attn[((long long)b*T_ + (t-1))*U_ + u] = s;
            g_aprev[b*U_ + u] = s;
        }
    }
}

// ---------------- z split-k partial ----------------
__global__ __launch_bounds__(128)
void z_partial(const float* __restrict__ Wx, const float* __restrict__ Wh, int t){
    __shared__ float xs[128][36];
    int tid = threadIdx.x;
    int kb  = blockIdx.y;
    int j   = blockIdx.x * 128 + tid;

    const float* xp; long long xst; const float* wp;
    if (kb < 4){
        xp  = g_emb + (long long)t*E_ + kb*128;
        xst = (long long)T_*E_;
        wp  = Wx + (long long)(kb*128)*4096;
    } else if (kb < 12){
        xp  = g_aprev + (kb-4)*128;
        xst = U_;
        wp  = Wx + (long long)(512 + (kb-4)*128)*4096;
    } else {
        xp  = g_h + (kb-12)*128;
        xst = U_;
        wp  = Wh + (long long)((kb-12)*128)*4096;
    }

    int b = tid >> 2, kq = tid & 3;
    #pragma unroll
    for (int i = 0; i < 8; i++){
        int k = kq*32 + i*4;
        float4 v = *(const float4*)(xp + b*xst + k);
        xs[k+0][b] = v.x; xs[k+1][b] = v.y; xs[k+2][b] = v.z; xs[k+3][b] = v.w;
    }
    __syncthreads();

    float acc[32];
    #pragma unroll
    for (int i = 0; i < 32; i++) acc[i] = 0.0f;

    const float* w = wp + j;
    #pragma unroll 4
    for (int k = 0; k < 128; k += 4){
        float w0 = w[(long long)(k+0)*4096];
        float w1 = w[(long long)(k+1)*4096];
        float w2 = w[(long long)(k+2)*4096];
        float w3 = w[(long long)(k+3)*4096];
        #pragma unroll
        for (int kk = 0; kk < 4; kk++){
            float wk = (kk==0)?w0:(kk==1)?w1:(kk==2)?w2:w3;
            #pragma unroll
            for (int b4 = 0; b4 < 8; b4++){
                float4 xv = *(const float4*)&xs[k+kk][b4*4];
                acc[b4*4+0] = fmaf(xv.x, wk, acc[b4*4+0]);
                acc[b4*4+1] = fmaf(xv.y, wk, acc[b4*4+1]);
                acc[b4*4+2] = fmaf(xv.z, wk, acc[b4*4+2]);
                acc[b4*4+3] = fmaf(xv.w, wk, acc[b4*4+3]);
            }
        }
    }
    #pragma unroll
    for (int bb = 0; bb < 32; bb++)
        g_zpart[((long long)kb*B_ + bb)*4096 + j] = acc[bb];
}

// ---------------- LSTM pointwise + z reduction ----------------
__global__ void lstm_pt(const float* __restrict__ bias){
    int idx = blockIdx.x * blockDim.x + threadIdx.x;
    if (idx >= B_*U_) return;
    int b = idx >> 10, u = idx & 1023;
    float zi = bias[u], zj = bias[U_+u], zf = bias[2*U_+u], zo = bias[3*U_+u];
    #pragma unroll
    for (int p = 0; p < 20; p++){
        const float* zp = g_zpart + ((long long)p*B_ + b)*4096;
        zi += zp[u]; zj += zp[U_+u]; zf += zp[2*U_+u]; zo += zp[3*U_+u];
    }
    float c  = g_c[idx];
    float cn = sigmoid_acc(zf + 1.0f) * c + sigmoid_acc(zi) * tanhf(zj);
    g_c[idx] = cn;
    g_h[idx] = sigmoid_acc(zo) * tanhf(cn);
}

// ---------------- q split-k partial ----------------
__global__ __launch_bounds__(128)
void q_partial(const float* __restrict__ Wq){
    __shared__ float xs[64][36];
    int tid = threadIdx.x;
    int kb  = blockIdx.y;
    int j   = blockIdx.x * 128 + tid;
    int r0  = kb * 64;

    int b = tid >> 2, kq = tid & 3;
    #pragma unroll
    for (int i = 0; i < 4; i++){
        int k = kq*16 + i*4;
        float4 v = *(const float4*)(g_h + b*U_ + r0 + k);
        xs[k+0][b] = v.x; xs[k+1][b] = v.y; xs[k+2][b] = v.z; xs[k+3][b] = v.w;
    }
    __syncthreads();

    float acc[32];
    #pragma unroll
    for (int i = 0; i < 32; i++) acc[i] = 0.0f;

    const float* w = Wq + (long long)r0*U_ + j;
    #pragma unroll 4
    for (int k = 0; k < 64; k += 4){
        float w0 = w[(long long)(k+0)*U_];
        float w1 = w[(long long)(k+1)*U_];
        float w2 = w[(long long)(k+2)*U_];
        float w3 = w[(long long)(k+3)*U_];
        #pragma unroll
        for (int kk = 0; kk < 4; kk++){
            float wk = (kk==0)?w0:(kk==1)?w1:(kk==2)?w2:w3;
            #pragma unroll
            for (int b4 = 0; b4 < 8; b4++){
                float4 xv = *(const float4*)&xs[k+kk][b4*4];
                acc[b4*4+0] = fmaf(xv.x, wk, acc[b4*4+0]);
                acc[b4*4+1] = fmaf(xv.y, wk, acc[b4*4+1]);
                acc[b4*4+2] = fmaf(xv.z, wk, acc[b4*4+2]);
                acc[b4*4+3] = fmaf(xv.w, wk, acc[b4*4+3]);
            }
        }
    }
    #pragma unroll
    for (int bb = 0; bb < 32; bb++)
        g_qpart[((long long)kb*B_ + bb)*U_ + j] = acc[bb];
}

// ---------------- scores + softmax + context ----------------
__global__ __launch_bounds__(512)
void attn_step(const float* __restrict__ enc, const float* __restrict__ v){
    int b = blockIdx.x;
    __shared__ float q_s[U_];
    __shared__ float sc_s[S_];
    __shared__ float al_s[S_];
    int tid = threadIdx.x;

    for (int u = tid; u < U_; u += 512){
        float s = 0.0f;
        #pragma unroll
        for (int p = 0; p < 16; p++)
            s += g_qpart[((long long)p*B_ + b)*U_ + u];
        q_s[u] = s;
    }
    __syncthreads();

    int warp = tid >> 5, lane = tid & 31;
    #pragma unroll
    for (int si = 0; si < 4; si++){
        int s = warp*4 + si;
        const float* kp = g_keys + (long long)(b*S_ + s)*U_;
        float p = 0.f;
        for (int u = lane; u < U_; u += 32)
            p = fmaf(tanh_fast(kp[u] + q_s[u]), v[u], p);
        #pragma unroll
        for (int off = 16; off; off >>= 1)
            p += __shfl_xor_sync(0xffffffffu, p, off);
        if (lane == 0) sc_s[s] = p;
    }
    __syncthreads();

    if (warp == 0){
        float s0 = sc_s[lane], s1 = sc_s[lane+32];
        float m = fmaxf(s0, s1);
        #pragma unroll
        for (int off = 16; off; off >>= 1)
            m = fmaxf(m, __shfl_xor_sync(0xffffffffu, m, off));
        float e0 = expf(s0 - m), e1 = expf(s1 - m);
        float sum = e0 + e1;
        #pragma unroll
        for (int off = 16; off; off >>= 1)
            sum += __shfl_xor_sync(0xffffffffu, sum, off);
        float inv = 1.0f / sum;
        al_s[lane]    = e0 * inv;
        al_s[lane+32] = e1 * inv;
    }
    __syncthreads();

    for (int e = tid; e < U_; e += 512){
        const float* ep = enc + (long long)b*S_*U_ + e;
        float a = 0.f;
        #pragma unroll 16
        for (int s = 0; s < S_; s++)
            a = fmaf(al_s[s], ep[(long long)s*U_], a);
        g_ctx[(long long)b*U_ + e] = a;
    }
}

// ---------------- attnout split-k partial ----------------
__global__ __launch_bounds__(128)
void attnout_partial(const float* __restrict__ Wa){
    __shared__ float xs[128][36];
    int tid = threadIdx.x;
    int kb  = blockIdx.y;
    int j   = blockIdx.x * 128 + tid;

    const float* xp = (kb < 8) ? (g_h + kb*128) : (g_ctx + (kb-8)*128);
    const float* wp = Wa + (long long)(kb*128)*U_;

    int b = tid >> 2, kq = tid & 3;
    #pragma unroll
    for (int i = 0; i < 8; i++){
        int k = kq*32 + i*4;
        float4 v = *(const float4*)(xp + b*U_ + k);
        xs[k+0][b] = v.x; xs[k+1][b] = v.y; xs[k+2][b] = v.z; xs[k+3][b] = v.w;
    }
    __syncthreads();

    float acc[32];
    #pragma unroll
    for (int i = 0; i < 32; i++) acc[i] = 0.0f;

    const float* w = wp + j;
    #pragma unroll 4
    for (int k = 0; k < 128; k += 4){
        float w0 = w[(long long)(k+0)*U_];
        float w1 = w[(long long)(k+1)*U_];
        float w2 = w[(long long)(k+2)*U_];
        float w3 = w[(long long)(k+3)*U_];
        #pragma unroll
        for (int kk = 0; kk < 4; kk++){
            float wk = (kk==0)?w0:(kk==1)?w1:(kk==2)?w2:w3;
            #pragma unroll
            for (int b4 = 0; b4 < 8; b4++){
                float4 xv = *(const float4*)&xs[k+kk][b4*4];
                acc[b4*4+0] = fmaf(xv.x, wk, acc[b4*4+0]);
                acc[b4*4+1] = fmaf(xv.y, wk, acc[b4*4+1]);
                acc[b4*4+2] = fmaf(xv.z, wk, acc[b4*4+2]);
                acc[b4*4+3] = fmaf(xv.w, wk, acc[b4*4+3]);
            }
        }
    }
    #pragma unroll
    for (int bb = 0; bb < 32; bb++)
        g_apart[((long long)kb*B_ + bb)*U_ + j] = acc[bb];
}

// ---------------- fp32 SGEMM (keys only) ----------------
__global__ __launch_bounds__(256)
void sgemm128(const float* __restrict__ A, const float* __restrict__ Bm,
              const float* __restrict__ bias, float* __restrict__ C,
              int M, int N, int K){
    __shared__ float As[16][132];
    __shared__ float Bs[16][132];
    int tid = threadIdx.x;
    int tx = tid & 15, ty = tid >> 4;
    int row0 = blockIdx.x * 128, col0 = blockIdx.y * 128;

    int m0 = tid >> 2, kq = tid & 3;
    int kr = tid >> 5, n4 = tid & 31;

    float acc[8][8];
    #pragma unroll
    for (int i = 0; i < 8; i++)
        #pragma unroll
        for (int j = 0; j < 8; j++) acc[i][j] = 0.0f;

    const float* Ap  = A  + (long long)(row0 + m0)*K + kq*4;
    const float* Ap2 = Ap + (long long)64*K;
    const float* Bp  = Bm + (long long)kr*N + col0 + n4*4;
    const float* Bp2 = Bp + (long long)8*N;

    float4 pa0 = *(const float4*)Ap;
    float4 pa1 = *(const float4*)Ap2;
    float4 pb0 = *(const float4*)Bp;
    float4 pb1 = *(const float4*)Bp2;

    int nk = K >> 4;
    for (int kt = 0; kt < nk; kt++){
        As[kq*4+0][m0]    = pa0.x; As[kq*4+1][m0]    = pa0.y;
        As[kq*4+2][m0]    = pa0.z; As[kq*4+3][m0]    = pa0.w;
        As[kq*4+0][m0+64] = pa1.x; As[kq*4+1][m0+64] = pa1.y;
        As[kq*4+2][m0+64] = pa1.z; As[kq*4+3][m0+64] = pa1.w;
        *(float4*)&Bs[kr][n4*4]   = pb0;
        *(float4*)&Bs[kr+8][n4*4] = pb1;
        __syncthreads();

        if (kt + 1 < nk){
            pa0 = *(const float4*)(Ap  + (kt+1)*16);
            pa1 = *(const float4*)(Ap2 + (kt+1)*16);
            pb0 = *(const float4*)(Bp  + (long long)(kt+1)*16*N);
            pb1 = *(const float4*)(Bp2 + (long long)(kt+1)*16*N);
        }

        #pragma unroll
        for (int k = 0; k < 16; k++){
            float a[8], bb[8];
            *(float4*)&a[0]  = *(const float4*)&As[k][ty*8];
            *(float4*)&a[4]  = *(const float4*)&As[k][ty*8+4];
            *(float4*)&bb[0] = *(const float4*)&Bs[k][tx*8];
            *(float4*)&bb[4] = *(const float4*)&Bs[k][tx*8+4];
            #pragma unroll
            for (int i = 0; i < 8; i++)
                #pragma unroll
                for (int j = 0; j < 8; j++)
                    acc[i][j] = fmaf(a[i], bb[j], acc[i][j]);
        }
        __syncthreads();
    }

    float bv[8];
    #pragma unroll
    for (int j = 0; j < 8; j++) bv[j] = bias ? bias[col0 + tx*8 + j] : 0.0f;

    #pragma unroll
    for (int i = 0; i < 8; i++){
        float* cp = C + (long long)(row0 + ty*8 + i)*N + col0 + tx*8;
        float4 o0, o1;
        o0.x = acc[i][0]+bv[0]; o0.y = acc[i][1]+bv[1];
        o0.z = acc[i][2]+bv[2]; o0.w = acc[i][3]+bv[3];
        o1.x = acc[i][4]+bv[4]; o1.y = acc[i][5]+bv[5];
        o1.z = acc[i][6]+bv[6]; o1.w = acc[i][7]+bv[7];
        *(float4*)cp       = o0;
        *(float4*)(cp + 4) = o1;
    }
}

// ---------------- bf16 split: attn -> Ah, Al ----------------
__global__ void split_attn(){
    int i = blockIdx.x * blockDim.x + threadIdx.x;
    if (i >= B_*T_*U_) return;
    float a = g_attn[i];
    __nv_bfloat16 h = __float2bfloat16(a);
    g_Ah[i] = h;
    g_Al[i] = __float2bfloat16(a - __bfloat162float(h));
}

// ---------------- bf16 split + transpose: Wout[K,V] -> Bh/Bl [V,K] ---------
__global__ __launch_bounds__(256)
void split_wout(const float* __restrict__ W){
    __shared__ float s[32][33];
    int n0 = blockIdx.x * 32, k0 = blockIdx.y * 32;
    int tx = threadIdx.x & 31, ty = threadIdx.x >> 5;   // 32 x 8
    #pragma unroll
    for (int i = 0; i < 32; i += 8)
        s[ty+i][tx] = W[(long long)(k0+ty+i)*V_ + n0 + tx];   // s[k][n]
    __syncthreads();
    #pragma unroll
    for (int i = 0; i < 32; i += 8){
        int n = ty + i;
        float a = s[tx][n];                         // k = tx
        __nv_bfloat16 h = __float2bfloat16(a);
        long long o = (long long)(n0+n)*U_ + k0 + tx;
        g_Bh[o] = h;
        g_Bl[o] = __float2bfloat16(a - __bfloat162float(h));
    }
}

// ================= tensor-core output GEMM via mma.sync (sm_80 PTX) ========
// out[2048,32000] = Ah@Bh^T + Al@Bh^T + Ah@Bl^T + bias, fp32 accum.
// Tiles: CTA 128x128xK32, 8 warps (2x4), warp 64x32, mma m16n8k16 bf16.
#define LDT   40                     // bf16 row stride in smem (32 + 8 pad)
#define TEN   (128*LDT)              // one tensor tile, bf16 elems (5120)
#define STAGE (4*TEN)                // Ah,Al,Bh,Bl per stage (20480 elems)
#define GM_SMEM (2*STAGE*2)          // bytes: 81920

#define MMA16816(c, a, b) \
    asm volatile("mma.sync.aligned.m16n8k16.row.col.f32.bf16.bf16.f32 " \
        "{%0,%1,%2,%3}, {%4,%5,%6,%7}, {%8,%9}, {%0,%1,%2,%3};" \
        : "+f"((c)[0]), "+f"((c)[1]), "+f"((c)[2]), "+f"((c)[3]) \
        : "r"((a)[0]), "r"((a)[1]), "r"((a)[2]), "r"((a)[3]), \
          "r"((b)[0]), "r"((b)[1]))

__global__ __launch_bounds__(256)
void gemm_mma(const float* __restrict__ bias, float* __restrict__ C){
    extern __shared__ __nv_bfloat16 sm[];
    const int tid  = threadIdx.x;
    const int lane = tid & 31, wid = tid >> 5;
    const int wm   = wid >> 2, wn = wid & 3;          // 2 x 4 warp grid
    const int g    = lane >> 2, c2 = (lane & 3) * 2;
    const long long row0 = (long long)blockIdx.x * 128;
    const long long col0 = (long long)blockIdx.y * 128;

    // global staging: each thread 2x16B per tensor per stage
    const int lr = tid >> 1;             // 0..127
    const int lc = (tid & 1) * 16;       // 0 or 16 (bf16 col)
    const __nv_bfloat16* srcs[4] = {
        g_Ah + (row0 + lr)*U_, g_Al + (row0 + lr)*U_,
        g_Bh + (col0 + lr)*U_, g_Bl + (col0 + lr)*U_ };

    float acc[4][4][4];
    #pragma unroll
    for (int mi = 0; mi < 4; mi++)
        #pragma unroll
        for (int ni = 0; ni < 4; ni++)
            #pragma unroll
            for (int q = 0; q < 4; q++) acc[mi][ni][q] = 0.0f;

    auto issue = [&](int kt, int buf){
        __nv_bfloat16* st = sm + buf*STAGE;
        #pragma unroll
        for (int tn = 0; tn < 4; tn++){
            uint32_t d = (uint32_t)__cvta_generic_to_shared(st + tn*TEN + lr*LDT + lc);
            const __nv_bfloat16* s = srcs[tn] + kt*32 + lc;
            asm volatile(
                "cp.async.cg.shared.global [%0], [%1], 16;\n\t"
                "cp.async.cg.shared.global [%2], [%3], 16;"
                :: "r"(d), "l"(s), "r"(d + 16), "l"(s + 8) : "memory");
        }
        asm volatile("cp.async.commit_group;" ::: "memory");
    };

    issue(0, 0);
    for (int kt = 0; kt < 32; kt++){
        int buf = kt & 1;
        if (kt + 1 < 32){
            issue(kt + 1, buf ^ 1);
            asm volatile("cp.async.wait_group 1;" ::: "memory");
        } else {
            asm volatile("cp.async.wait_group 0;" ::: "memory");
        }
        __syncthreads();

        const __nv_bfloat16* st = sm + buf*STAGE;
        const __nv_bfloat16* Ah = st + wm*64*LDT;
        const __nv_bfloat16* Al = Ah + TEN;
        const __nv_bfloat16* Bh = st + 2*TEN + wn*32*LDT;
        const __nv_bfloat16* Bl = Bh + TEN;

        #pragma unroll
        for (int ks = 0; ks < 32; ks += 16){
            uint32_t bh[4][2], bl[4][2];
            #pragma unroll
            for (int ni = 0; ni < 4; ni++){
                const __nv_bfloat16* bp  = Bh + (ni*8 + g)*LDT + ks + c2;
                const __nv_bfloat16* blp = Bl + (ni*8 + g)*LDT + ks + c2;
                bh[ni][0] = *(const uint32_t*)bp;
                bh[ni][1] = *(const uint32_t*)(bp + 8);
                bl[ni][0] = *(const uint32_t*)blp;
                bl[ni][1] = *(const uint32_t*)(blp + 8);
            }
            #pragma unroll
            for (int mi = 0; mi < 4; mi++){
                const __nv_bfloat16* ap  = Ah + (mi*16 + g)*LDT + ks + c2;
                const __nv_bfloat16* alp = Al + (mi*16 + g)*LDT + ks + c2;
                uint32_t ah[4], al[4];
                ah[0] = *(const uint32_t*)ap;
                ah[1] = *(const uint32_t*)(ap + 8*LDT);
                ah[2] = *(const uint32_t*)(ap + 8);
                ah[3] = *(const uint32_t*)(ap + 8*LDT + 8);
                al[0] = *(const uint32_t*)alp;
                al[1] = *(const uint32_t*)(alp + 8*LDT);
                al[2] = *(const uint32_t*)(alp + 8);
                al[3] = *(const uint32_t*)(alp + 8*LDT + 8);
                #pragma unroll
                for (int ni = 0; ni < 4; ni++){
                    MMA16816(acc[mi][ni], ah, bh[ni]);
                    MMA16816(acc[mi][ni], al, bh[ni]);
                    MMA16816(acc[mi][ni], ah, bl[ni]);
                }
            }
        }
        __syncthreads();
    }

    // epilogue: fused bias, float2 stores
    #pragma unroll
    for (int mi = 0; mi < 4; mi++){
        long long r = row0 + wm*64 + mi*16 + g;
        #pragma unroll
        for (int ni = 0; ni < 4; ni++){
            long long cc = col0 + wn*32 + ni*8 + c2;
            float b0 = bias[cc], b1 = bias[cc + 1];
            float2 v0, v1;
            v0.x = acc[mi][ni][0] + b0; v0.y = acc[mi][ni][1] + b1;
            v1.x = acc[mi][ni][2] + b0; v1.y = acc[mi][ni][3] + b1;
            *(float2*)(C + r*V_ + cc)       = v0;
            *(float2*)(C + (r + 8)*V_ + cc) = v1;
        }
    }
}

// ---------------- launch -----------------------------------------------------
extern "C" void kernel_launch(void* const* d_in, const int* in_sizes, int n_in,
                              void* d_out, int out_size){
    const int*   y     = (const int*)  d_in[0];
    const float* h0    = (const float*)d_in[1];
    const float* c0    = (const float*)d_in[2];
    const float* enc   = (const float*)d_in[3];
    const float* emb   = (const float*)d_in[4];
    const float* Wx    = (const float*)d_in[5];
    const float* Wh    = (const float*)d_in[6];
    const float* bvec  = (const float*)d_in[7];
    const float* Wk    = (const float*)d_in[8];
    const float* Wq    = (const float*)d_in[9];
    const float* v_att = (const float*)d_in[10];
    const float* Wa    = (const float*)d_in[11];
    const float* Wout  = (const float*)d_in[12];
    const float* bout  = (const float*)d_in[13];
    float* out = (float*)d_out;

    void* p;
    cudaGetSymbolAddress(&p, g_keys); float* keys_p = (float*)p;

    cudaFuncSetAttribute(gemm_mma, cudaFuncAttributeMaxDynamicSharedMemorySize, GM_SMEM);

    init_hc<<<128, 256>>>(h0, c0);
    embed_gather<<<B_*T_, 128>>>(y, emb);

    // Wout bf16 split+transpose (independent of the loop; overlaps on GPU)
    split_wout<<<dim3(V_/32, U_/32), 256>>>(Wout);

    // keys = enc @ Wk
    sgemm128<<<dim3((B_*S_)/128, U_/128), 256>>>(enc, Wk, nullptr, keys_p,
                                                 B_*S_, U_, U_);

    for (int t = 0; t < T_; t++){
        prep_step<<<32, 256>>>(t);
        z_partial<<<dim3(32, 20), 128>>>(Wx, Wh, t);
        lstm_pt<<<128, 256>>>(bvec);
        q_partial<<<dim3(8, 16), 128>>>(Wq);
        attn_step<<<32, 512>>>(enc, v_att);
        attnout_partial<<<dim3(8, 16), 128>>>(Wa);
    }
    prep_step<<<32, 256>>>(T_);

    // bf16 split of attn activations, then tensor-core output GEMM
    split_attn<<<(B_*T_*U_ + 255)/256, 256>>>();
    gemm_mma<<<dim3((B_*T_)/128, V_/128), 256, GM_SMEM>>>(bout, out);
}

// round 12
// speedup vs baseline: 5.5275x; 1.0516x over previous
#include <cuda_runtime.h>
#include <cuda_bf16.h>
#include <math.h>
#include <stdint.h>

#define B_ 32
#define T_ 64
#define S_ 64
#define V_ 32000
#define E_ 512
#define U_ 1024

// ---------------- scratch (static device globals; no allocs) ----------------
__device__ float g_emb  [B_*T_*E_];
__device__ float g_keys [B_*S_*U_];
__device__ float g_attn [B_*T_*U_];
__device__ float g_zpart[20*B_*4*U_];
__device__ float g_qpart[16*B_*U_];
__device__ float g_apart[16*B_*U_];
__device__ float g_aprev[B_*U_];
__device__ float g_h    [B_*U_];
__device__ float g_c    [B_*U_];
__device__ float g_ctx  [B_*U_];
// bf16-split operands for tensor-core output GEMM
__device__ __nv_bfloat16 g_Ah[B_*T_*U_];     // attn hi   [2048][1024] k-major
__device__ __nv_bfloat16 g_Al[B_*T_*U_];     // attn lo
__device__ __nv_bfloat16 g_Bh[V_*U_];        // Wout^T hi [32000][1024] n-major
__device__ __nv_bfloat16 g_Bl[V_*U_];        // Wout^T lo

__device__ __forceinline__ float tanh_fast(float x){
    float r; asm("tanh.approx.f32 %0, %1;" : "=f"(r) : "f"(x)); return r;
}
__device__ __forceinline__ float sigmoid_acc(float x){
    return 1.0f / (1.0f + expf(-x));
}

// ---- packed f32x2 helpers (sm_100-family base PTX) ----
__device__ __forceinline__ unsigned long long pack2(float a, float b){
    unsigned long long r;
    asm("mov.b64 %0, {%1, %2};" : "=l"(r) : "f"(a), "f"(b));
    return r;
}
__device__ __forceinline__ void unpack2(unsigned long long v, float& a, float& b){
    asm("mov.b64 {%0, %1}, %2;" : "=f"(a), "=f"(b) : "l"(v));
}
#define FMA2(acc, x, w) \
    asm("fma.rn.f32x2 %0, %1, %2, %0;" : "+l"(acc) : "l"(x), "l"(w))

// ---------------- init h/c ----------------
__global__ void init_hc(const float* __restrict__ h0, const float* __restrict__ c0){
    int i = blockIdx.x * blockDim.x + threadIdx.x;
    if (i < B_*U_){ g_h[i] = h0[i]; g_c[i] = c0[i]; }
}

// ---------------- embedding gather ----------------
__global__ void embed_gather(const int* __restrict__ y, const float* __restrict__ emb){
    int bt = blockIdx.x;
    int b = bt / T_, t = bt % T_;
    int tok = (t == 0) ? 1 : y[b*T_ + t - 1];
    const float4* src = (const float4*)(emb + (long long)tok * E_);
    float4* dst = (float4*)(g_emb + (long long)bt * E_);
    int i = threadIdx.x;
    if (i < E_/4) dst[i] = src[i];
}

// ---------------- prep: reduce attnout partials of step t-1 ----------------
__global__ void prep_step(int t){
    int b = blockIdx.x;
    for (int u = threadIdx.x; u < U_; u += 256){
        if (t == 0){
            g_aprev[b*U_ + u] = 0.0f;
        } else {
            float s = 0.0f;
            #pragma unroll
            for (int p = 0; p < 16; p++)
                s += g_apart[(p*B_ + b)*U_ + u];
            g_attn[((long long)b*T_ + (t-1))*U_ + u] = s;
            g_aprev[b*U_ + u] = s;
        }
    }
}

// ---------------- z split-k partial (f32x2) ----------------
__global__ __launch_bounds__(128)
void z_partial(const float* __restrict__ Wx, const float* __restrict__ Wh, int t){
    __shared__ float xs[128][36];
    int tid = threadIdx.x;
    int kb  = blockIdx.y;
    int j   = blockIdx.x * 128 + tid;

    const float* xp; long long xst; const float* wp;
    if (kb < 4){
        xp  = g_emb + (long long)t*E_ + kb*128;
        xst = (long long)T_*E_;
        wp  = Wx + (long long)(kb*128)*4096;
    } else if (kb < 12){
        xp  = g_aprev + (kb-4)*128;
        xst = U_;
        wp  = Wx + (long long)(512 + (kb-4)*128)*4096;
    } else {
        xp  = g_h + (kb-12)*128;
        xst = U_;
        wp  = Wh + (long long)((kb-12)*128)*4096;
    }

    int b = tid >> 2, kq = tid & 3;
    #pragma unroll
    for (int i = 0; i < 8; i++){
        int k = kq*32 + i*4;
        float4 v = *(const float4*)(xp + b*xst + k);
        xs[k+0][b] = v.x; xs[k+1][b] = v.y; xs[k+2][b] = v.z; xs[k+3][b] = v.w;
    }
    __syncthreads();

    unsigned long long acc2[16];
    #pragma unroll
    for (int i = 0; i < 16; i++) acc2[i] = 0ull;

    const float* w = wp + j;
    #pragma unroll 4
    for (int k = 0; k < 128; k += 4){
        float w0 = w[(long long)(k+0)*4096];
        float w1 = w[(long long)(k+1)*4096];
        float w2 = w[(long long)(k+2)*4096];
        float w3 = w[(long long)(k+3)*4096];
        #pragma unroll
        for (int kk = 0; kk < 4; kk++){
            float wk = (kk==0)?w0:(kk==1)?w1:(kk==2)?w2:w3;
            unsigned long long wk2 = pack2(wk, wk);
            #pragma unroll
            for (int b4 = 0; b4 < 8; b4++){
                float4 xv = *(const float4*)&xs[k+kk][b4*4];
                unsigned long long x01 = pack2(xv.x, xv.y);
                unsigned long long x23 = pack2(xv.z, xv.w);
                FMA2(acc2[b4*2+0], x01, wk2);
                FMA2(acc2[b4*2+1], x23, wk2);
            }
        }
    }
    #pragma unroll
    for (int p = 0; p < 16; p++){
        float v0, v1; unpack2(acc2[p], v0, v1);
        g_zpart[((long long)kb*B_ + 2*p+0)*4096 + j] = v0;
        g_zpart[((long long)kb*B_ + 2*p+1)*4096 + j] = v1;
    }
}

// ---------------- LSTM pointwise + z reduction ----------------
__global__ void lstm_pt(const float* __restrict__ bias){
    int idx = blockIdx.x * blockDim.x + threadIdx.x;
    if (idx >= B_*U_) return;
    int b = idx >> 10, u = idx & 1023;
    float zi = bias[u], zj = bias[U_+u], zf = bias[2*U_+u], zo = bias[3*U_+u];
    #pragma unroll
    for (int p = 0; p < 20; p++){
        const float* zp = g_zpart + ((long long)p*B_ + b)*4096;
        zi += zp[u]; zj += zp[U_+u]; zf += zp[2*U_+u]; zo += zp[3*U_+u];
    }
    float c  = g_c[idx];
    float cn = sigmoid_acc(zf + 1.0f) * c + sigmoid_acc(zi) * tanhf(zj);
    g_c[idx] = cn;
    g_h[idx] = sigmoid_acc(zo) * tanhf(cn);
}

// ---------------- q split-k partial (f32x2) ----------------
__global__ __launch_bounds__(128)
void q_partial(const float* __restrict__ Wq){
    __shared__ float xs[64][36];
    int tid = threadIdx.x;
    int kb  = blockIdx.y;
    int j   = blockIdx.x * 128 + tid;
    int r0  = kb * 64;

    int b = tid >> 2, kq = tid & 3;
    #pragma unroll
    for (int i = 0; i < 4; i++){
        int k = kq*16 + i*4;
        float4 v = *(const float4*)(g_h + b*U_ + r0 + k);
        xs[k+0][b] = v.x; xs[k+1][b] = v.y; xs[k+2][b] = v.z; xs[k+3][b] = v.w;
    }
    __syncthreads();

    unsigned long long acc2[16];
    #pragma unroll
    for (int i = 0; i < 16; i++) acc2[i] = 0ull;

    const float* w = Wq + (long long)r0*U_ + j;
    #pragma unroll 4
    for (int k = 0; k < 64; k += 4){
        float w0 = w[(long long)(k+0)*U_];
        float w1 = w[(long long)(k+1)*U_];
        float w2 = w[(long long)(k+2)*U_];
        float w3 = w[(long long)(k+3)*U_];
        #pragma unroll
        for (int kk = 0; kk < 4; kk++){
            float wk = (kk==0)?w0:(kk==1)?w1:(kk==2)?w2:w3;
            unsigned long long wk2 = pack2(wk, wk);
            #pragma unroll
            for (int b4 = 0; b4 < 8; b4++){
                float4 xv = *(const float4*)&xs[k+kk][b4*4];
                unsigned long long x01 = pack2(xv.x, xv.y);
                unsigned long long x23 = pack2(xv.z, xv.w);
                FMA2(acc2[b4*2+0], x01, wk2);
                FMA2(acc2[b4*2+1], x23, wk2);
            }
        }
    }
    #pragma unroll
    for (int p = 0; p < 16; p++){
        float v0, v1; unpack2(acc2[p], v0, v1);
        g_qpart[((long long)kb*B_ + 2*p+0)*U_ + j] = v0;
        g_qpart[((long long)kb*B_ + 2*p+1)*U_ + j] = v1;
    }
}

// ---------------- scores + softmax + context ----------------
__global__ __launch_bounds__(512)
void attn_step(const float* __restrict__ enc, const float* __restrict__ v){
    int b = blockIdx.x;
    __shared__ float q_s[U_];
    __shared__ float sc_s[S_];
    __shared__ float al_s[S_];
    int tid = threadIdx.x;

    for (int u = tid; u < U_; u += 512){
        float s = 0.0f;
        #pragma unroll
        for (int p = 0; p < 16; p++)
            s += g_qpart[((long long)p*B_ + b)*U_ + u];
        q_s[u] = s;
    }
    __syncthreads();

    int warp = tid >> 5, lane = tid & 31;
    #pragma unroll
    for (int si = 0; si < 4; si++){
        int s = warp*4 + si;
        const float* kp = g_keys + (long long)(b*S_ + s)*U_;
        float p = 0.f;
        for (int u = lane; u < U_; u += 32)
            p = fmaf(tanh_fast(kp[u] + q_s[u]), v[u], p);
        #pragma unroll
        for (int off = 16; off; off >>= 1)
            p += __shfl_xor_sync(0xffffffffu, p, off);
        if (lane == 0) sc_s[s] = p;
    }
    __syncthreads();

    if (warp == 0){
        float s0 = sc_s[lane], s1 = sc_s[lane+32];
        float m = fmaxf(s0, s1);
        #pragma unroll
        for (int off = 16; off; off >>= 1)
            m = fmaxf(m, __shfl_xor_sync(0xffffffffu, m, off));
        float e0 = expf(s0 - m), e1 = expf(s1 - m);
        float sum = e0 + e1;
        #pragma unroll
        for (int off = 16; off; off >>= 1)
            sum += __shfl_xor_sync(0xffffffffu, sum, off);
        float inv = 1.0f / sum;
        al_s[lane]    = e0 * inv;
        al_s[lane+32] = e1 * inv;
    }
    __syncthreads();

    for (int e = tid; e < U_; e += 512){
        const float* ep = enc + (long long)b*S_*U_ + e;
        float a = 0.f;
        #pragma unroll 16
        for (int s = 0; s < S_; s++)
            a = fmaf(al_s[s], ep[(long long)s*U_], a);
        g_ctx[(long long)b*U_ + e] = a;
    }
}

// ---------------- attnout split-k partial (f32x2) ----------------
__global__ __launch_bounds__(128)
void attnout_partial(const float* __restrict__ Wa){
    __shared__ float xs[128][36];
    int tid = threadIdx.x;
    int kb  = blockIdx.y;
    int j   = blockIdx.x * 128 + tid;

    const float* xp = (kb < 8) ? (g_h + kb*128) : (g_ctx + (kb-8)*128);
    const float* wp = Wa + (long long)(kb*128)*U_;

    int b = tid >> 2, kq = tid & 3;
    #pragma unroll
    for (int i = 0; i < 8; i++){
        int k = kq*32 + i*4;
        float4 v = *(const float4*)(xp + b*U_ + k);
        xs[k+0][b] = v.x; xs[k+1][b] = v.y; xs[k+2][b] = v.z; xs[k+3][b] = v.w;
    }
    __syncthreads();

    unsigned long long acc2[16];
    #pragma unroll
    for (int i = 0; i < 16; i++) acc2[i] = 0ull;

    const float* w = wp + j;
    #pragma unroll 4
    for (int k = 0; k < 128; k += 4){
        float w0 = w[(long long)(k+0)*U_];
        float w1 = w[(long long)(k+1)*U_];
        float w2 = w[(long long)(k+2)*U_];
        float w3 = w[(long long)(k+3)*U_];
        #pragma unroll
        for (int kk = 0; kk < 4; kk++){
            float wk = (kk==0)?w0:(kk==1)?w1:(kk==2)?w2:w3;
            unsigned long long wk2 = pack2(wk, wk);
            #pragma unroll
            for (int b4 = 0; b4 < 8; b4++){
                float4 xv = *(const float4*)&xs[k+kk][b4*4];
                unsigned long long x01 = pack2(xv.x, xv.y);
                unsigned long long x23 = pack2(xv.z, xv.w);
                FMA2(acc2[b4*2+0], x01, wk2);
                FMA2(acc2[b4*2+1], x23, wk2);
            }
        }
    }
    #pragma unroll
    for (int p = 0; p < 16; p++){
        float v0, v1; unpack2(acc2[p], v0, v1);
        g_apart[((long long)kb*B_ + 2*p+0)*U_ + j] = v0;
        g_apart[((long long)kb*B_ + 2*p+1)*U_ + j] = v1;
    }
}

// ---------------- fp32 SGEMM (keys only, f32x2) ----------------
__global__ __launch_bounds__(256)
void sgemm128(const float* __restrict__ A, const float* __restrict__ Bm,
              const float* __restrict__ bias, float* __restrict__ C,
              int M, int N, int K){
    __shared__ float As[16][132];
    __shared__ float Bs[16][132];
    int tid = threadIdx.x;
    int tx = tid & 15, ty = tid >> 4;
    int row0 = blockIdx.x * 128, col0 = blockIdx.y * 128;

    int m0 = tid >> 2, kq = tid & 3;
    int kr = tid >> 5, n4 = tid & 31;

    unsigned long long acc2[8][4];
    #pragma unroll
    for (int i = 0; i < 8; i++)
        #pragma unroll
        for (int j = 0; j < 4; j++) acc2[i][j] = 0ull;

    const float* Ap  = A  + (long long)(row0 + m0)*K + kq*4;
    const float* Ap2 = Ap + (long long)64*K;
    const float* Bp  = Bm + (long long)kr*N + col0 + n4*4;
    const float* Bp2 = Bp + (long long)8*N;

    float4 pa0 = *(const float4*)Ap;
    float4 pa1 = *(const float4*)Ap2;
    float4 pb0 = *(const float4*)Bp;
    float4 pb1 = *(const float4*)Bp2;

    int nk = K >> 4;
    for (int kt = 0; kt < nk; kt++){
        As[kq*4+0][m0]    = pa0.x; As[kq*4+1][m0]    = pa0.y;
        As[kq*4+2][m0]    = pa0.z; As[kq*4+3][m0]    = pa0.w;
        As[kq*4+0][m0+64] = pa1.x; As[kq*4+1][m0+64] = pa1.y;
        As[kq*4+2][m0+64] = pa1.z; As[kq*4+3][m0+64] = pa1.w;
        *(float4*)&Bs[kr][n4*4]   = pb0;
        *(float4*)&Bs[kr+8][n4*4] = pb1;
        __syncthreads();

        if (kt + 1 < nk){
            pa0 = *(const float4*)(Ap  + (kt+1)*16);
            pa1 = *(const float4*)(Ap2 + (kt+1)*16);
            pb0 = *(const float4*)(Bp  + (long long)(kt+1)*16*N);
            pb1 = *(const float4*)(Bp2 + (long long)(kt+1)*16*N);
        }

        #pragma unroll
        for (int k = 0; k < 16; k++){
            float a[8];
            *(float4*)&a[0]  = *(const float4*)&As[k][ty*8];
            *(float4*)&a[4]  = *(const float4*)&As[k][ty*8+4];
            float4 b0 = *(const float4*)&Bs[k][tx*8];
            float4 b1 = *(const float4*)&Bs[k][tx*8+4];
            unsigned long long bb2[4];
            bb2[0] = pack2(b0.x, b0.y); bb2[1] = pack2(b0.z, b0.w);
            bb2[2] = pack2(b1.x, b1.y); bb2[3] = pack2(b1.z, b1.w);
            #pragma unroll
            for (int i = 0; i < 8; i++){
                unsigned long long ai = pack2(a[i], a[i]);
                #pragma unroll
                for (int j = 0; j < 4; j++)
                    FMA2(acc2[i][j], bb2[j], ai);
            }
        }
        __syncthreads();
    }

    float bv[8];
    #pragma unroll
    for (int j = 0; j < 8; j++) bv[j] = bias ? bias[col0 + tx*8 + j] : 0.0f;

    #pragma unroll
    for (int i = 0; i < 8; i++){
        float* cp = C + (long long)(row0 + ty*8 + i)*N + col0 + tx*8;
        float o[8];
        #pragma unroll
        for (int j = 0; j < 4; j++) unpack2(acc2[i][j], o[2*j], o[2*j+1]);
        float4 o0, o1;
        o0.x = o[0]+bv[0]; o0.y = o[1]+bv[1]; o0.z = o[2]+bv[2]; o0.w = o[3]+bv[3];
        o1.x = o[4]+bv[4]; o1.y = o[5]+bv[5]; o1.z = o[6]+bv[6]; o1.w = o[7]+bv[7];
        *(float4*)cp       = o0;
        *(float4*)(cp + 4) = o1;
    }
}

// ---------------- bf16 split: attn -> Ah, Al ----------------
__global__ void split_attn(){
    int i = blockIdx.x * blockDim.x + threadIdx.x;
    if (i >= B_*T_*U_) return;
    float a = g_attn[i];
    __nv_bfloat16 h = __float2bfloat16(a);
    g_Ah[i] = h;
    g_Al[i] = __float2bfloat16(a - __bfloat162float(h));
}

// ---------------- bf16 split + transpose: Wout[K,V] -> Bh/Bl [V,K] ---------
__global__ __launch_bounds__(256)
void split_wout(const float* __restrict__ W){
    __shared__ float s[32][33];
    int n0 = blockIdx.x * 32, k0 = blockIdx.y * 32;
    int tx = threadIdx.x & 31, ty = threadIdx.x >> 5;   // 32 x 8
    #pragma unroll
    for (int i = 0; i < 32; i += 8)
        s[ty+i][tx] = W[(long long)(k0+ty+i)*V_ + n0 + tx];   // s[k][n]
    __syncthreads();
    #pragma unroll
    for (int i = 0; i < 32; i += 8){
        int n = ty + i;
        float a = s[tx][n];                         // k = tx
        __nv_bfloat16 h = __float2bfloat16(a);
        long long o = (long long)(n0+n)*U_ + k0 + tx;
        g_Bh[o] = h;
        g_Bl[o] = __float2bfloat16(a - __bfloat162float(h));
    }
}

// ================= tensor-core output GEMM via mma.sync + ldmatrix =========
// out[2048,32000] = Ah@Bh^T + Al@Bh^T + Ah@Bl^T + bias, fp32 accum.
// Tiles: CTA 128x128xK32, 8 warps (2x4), warp 64x32, mma m16n8k16 bf16.
#define LDT     40                     // bf16 row stride in smem (32 + 8 pad)
#define TEN     (128*LDT)              // one tensor tile, bf16 elems (5120)
#define TEN_B   (TEN*2)                // bytes (10240)
#define STAGE   (4*TEN)                // Ah,Al,Bh,Bl per stage (elems)
#define STAGE_B (STAGE*2)              // bytes (40960)
#define GM_SMEM (2*STAGE_B)            // 81920

#define MMA16816(c, a, b) \
    asm volatile("mma.sync.aligned.m16n8k16.row.col.f32.bf16.bf16.f32 " \
        "{%0,%1,%2,%3}, {%4,%5,%6,%7}, {%8,%9}, {%0,%1,%2,%3};" \
        : "+f"((c)[0]), "+f"((c)[1]), "+f"((c)[2]), "+f"((c)[3]) \
        : "r"((a)[0]), "r"((a)[1]), "r"((a)[2]), "r"((a)[3]), \
          "r"((b)[0]), "r"((b)[1]))

#define LDSM4(R0, R1, R2, R3, ADDR) \
    asm volatile("ldmatrix.sync.aligned.m8n8.x4.shared.b16 {%0,%1,%2,%3}, [%4];" \
        : "=r"(R0), "=r"(R1), "=r"(R2), "=r"(R3) : "r"(ADDR))

__global__ __launch_bounds__(256)
void gemm_mma(const float* __restrict__ bias, float* __restrict__ C){
    extern __shared__ __nv_bfloat16 sm[];
    const int tid  = threadIdx.x;
    const int lane = tid & 31, wid = tid >> 5;
    const int wm   = wid >> 2, wn = wid & 3;          // 2 x 4 warp grid
    const int g    = lane >> 2, c2 = (lane & 3) * 2;
    const long long row0 = (long long)blockIdx.x * 128;
    const long long col0 = (long long)blockIdx.y * 128;

    const uint32_t smb = (uint32_t)__cvta_generic_to_shared(sm);

    // ldmatrix per-lane address components (element units)
    // A (x4): mat0 rows+0 col+0, mat1 rows+8 col+0, mat2 rows+0 col+8, mat3 rows+8 col+8
    const uint32_t a_elem = (uint32_t)(wm*64 + ((lane>>3)&1)*8 + (lane&7)) * LDT
                          + (uint32_t)((lane>>4)*8);
    // B (x4, pair p): mat0 (n 2p+0, k0-7), mat1 (n 2p+0, k8-15), mat2 (n 2p+1, k0-7), mat3 (n 2p+1, k8-15)
    uint32_t b_elem[2];
    #pragma unroll
    for (int p = 0; p < 2; p++)
        b_elem[p] = (uint32_t)(wn*32 + p*16 + (lane>>4)*8 + (lane&7)) * LDT
                  + (uint32_t)(((lane>>3)&1)*8);

    // global staging: each thread 2x16B per tensor per stage
    const int lr = tid >> 1;             // 0..127
    const int lc = (tid & 1) * 16;       // 0 or 16 (bf16 col)
    const __nv_bfloat16* srcs[4] = {
        g_Ah + (row0 + lr)*U_, g_Al + (row0 + lr)*U_,
        g_Bh + (col0 + lr)*U_, g_Bl + (col0 + lr)*U_ };

    float acc[4][4][4];
    #pragma unroll
    for (int mi = 0; mi < 4; mi++)
        #pragma unroll
        for (int ni = 0; ni < 4; ni++)
            #pragma unroll
            for (int q = 0; q < 4; q++) acc[mi][ni][q] = 0.0f;

    auto issue = [&](int kt, int buf){
        __nv_bfloat16* st = sm + buf*STAGE;
        #pragma unroll
        for (int tn = 0; tn < 4; tn++){
            uint32_t d = (uint32_t)__cvta_generic_to_shared(st + tn*TEN + lr*LDT + lc);
            const __nv_bfloat16* s = srcs[tn] + kt*32 + lc;
            asm volatile(
                "cp.async.cg.shared.global [%0], [%1], 16;\n\t"
                "cp.async.cg.shared.global [%2], [%3], 16;"
                :: "r"(d), "l"(s), "r"(d + 16), "l"(s + 8) : "memory");
        }
        asm volatile("cp.async.commit_group;" ::: "memory");
    };

    issue(0, 0);
    for (int kt = 0; kt < 32; kt++){
        int buf = kt & 1;
        if (kt + 1 < 32){
            issue(kt + 1, buf ^ 1);
            asm volatile("cp.async.wait_group 1;" ::: "memory");
        } else {
            asm volatile("cp.async.wait_group 0;" ::: "memory");
        }
        __syncthreads();

        const uint32_t stage_b = smb + buf*STAGE_B;

        #pragma unroll
        for (int ks = 0; ks < 32; ks += 16){
            // B fragments: bh/bl for 4 ni via 4 ldmatrix.x4
            uint32_t bh[4][2], bl[4][2];
            #pragma unroll
            for (int p = 0; p < 2; p++){
                uint32_t ab = stage_b + 2*TEN_B + (b_elem[p] + ks)*2;
                LDSM4(bh[2*p][0], bh[2*p][1], bh[2*p+1][0], bh[2*p+1][1], ab);
                uint32_t al_ = stage_b + 3*TEN_B + (b_elem[p] + ks)*2;
                LDSM4(bl[2*p][0], bl[2*p][1], bl[2*p+1][0], bl[2*p+1][1], al_);
            }
            #pragma unroll
            for (int mi = 0; mi < 4; mi++){
                uint32_t ah[4], al[4];
                uint32_t aa = stage_b + (a_elem + mi*16*LDT + ks)*2;
                LDSM4(ah[0], ah[1], ah[2], ah[3], aa);
                uint32_t ab = stage_b + TEN_B + (a_elem + mi*16*LDT + ks)*2;
                LDSM4(al[0], al[1], al[2], al[3], ab);
                #pragma unroll
                for (int ni = 0; ni < 4; ni++){
                    MMA16816(acc[mi][ni], ah, bh[ni]);
                    MMA16816(acc[mi][ni], al, bh[ni]);
                    MMA16816(acc[mi][ni], ah, bl[ni]);
                }
            }
        }
        __syncthreads();
    }

    // epilogue: fused bias, float2 stores
    #pragma unroll
    for (int mi = 0; mi < 4; mi++){
        long long r = row0 + wm*64 + mi*16 + g;
        #pragma unroll
        for (int ni = 0; ni < 4; ni++){
            long long cc = col0 + wn*32 + ni*8 + c2;
            float b0 = bias[cc], b1 = bias[cc + 1];
            float2 v0, v1;
            v0.x = acc[mi][ni][0] + b0; v0.y = acc[mi][ni][1] + b1;
            v1.x = acc[mi][ni][2] + b0; v1.y = acc[mi][ni][3] + b1;
            *(float2*)(C + r*V_ + cc)       = v0;
            *(float2*)(C + (r + 8)*V_ + cc) = v1;
        }
    }
}

// ---------------- launch -----------------------------------------------------
extern "C" void kernel_launch(void* const* d_in, const int* in_sizes, int n_in,
                              void* d_out, int out_size){
    const int*   y     = (const int*)  d_in[0];
    const float* h0    = (const float*)d_in[1];
    const float* c0    = (const float*)d_in[2];
    const float* enc   = (const float*)d_in[3];
    const float* emb   = (const float*)d_in[4];
    const float* Wx    = (const float*)d_in[5];
    const float* Wh    = (const float*)d_in[6];
    const float* bvec  = (const float*)d_in[7];
    const float* Wk    = (const float*)d_in[8];
    const float* Wq    = (const float*)d_in[9];
    const float* v_att = (const float*)d_in[10];
    const float* Wa    = (const float*)d_in[11];
    const float* Wout  = (const float*)d_in[12];
    const float* bout  = (const float*)d_in[13];
    float* out = (float*)d_out;

    void* p;
    cudaGetSymbolAddress(&p, g_keys); float* keys_p = (float*)p;

    cudaFuncSetAttribute(gemm_mma, cudaFuncAttributeMaxDynamicSharedMemorySize, GM_SMEM);

    init_hc<<<128, 256>>>(h0, c0);
    embed_gather<<<B_*T_, 128>>>(y, emb);

    // Wout bf16 split+transpose (independent of the loop; overlaps on GPU)
    split_wout<<<dim3(V_/32, U_/32), 256>>>(Wout);

    // keys = enc @ Wk
    sgemm128<<<dim3((B_*S_)/128, U_/128), 256>>>(enc, Wk, nullptr, keys_p,
                                                 B_*S_, U_, U_);

    for (int t = 0; t < T_; t++){
        prep_step<<<32, 256>>>(t);
        z_partial<<<dim3(32, 20), 128>>>(Wx, Wh, t);
        lstm_pt<<<128, 256>>>(bvec);
        q_partial<<<dim3(8, 16), 128>>>(Wq);
        attn_step<<<32, 512>>>(enc, v_att);
        attnout_partial<<<dim3(8, 16), 128>>>(Wa);
    }
    prep_step<<<32, 256>>>(T_);

    // bf16 split of attn activations, then tensor-core output GEMM
    split_attn<<<(B_*T_*U_ + 255)/256, 256>>>();
    gemm_mma<<<dim3((B_*T_)/128, V_/128), 256, GM_SMEM>>>(bout, out);
}